// round 7
// baseline (speedup 1.0000x reference)
#include <cuda_runtime.h>
#include <cstdint>
#include <math.h>

#define TT   16
#define MTOT 2048
#define HH   2048
#define DIN  1024
#define DOUT 1024

#define NTHR 384              // 12 warps: 2(M) x 2(N) x 3(plane)
#define PTHR 512
#define KCB  128              // int8 k per chunk
#define STAGEB 65536          // A(16KB) + 3 B planes(48KB)

// ---------------- static device scratch ----------------
__device__ __align__(1024) int8_t g_A0 [(size_t)MTOT * DIN];
__device__ __align__(1024) int8_t g_s0 [(size_t)MTOT * HH];
__device__ __align__(1024) int8_t g_s1 [(size_t)MTOT * HH];
__device__ __align__(1024) int8_t g_W0q[(size_t)HH   * 3 * DIN];
__device__ __align__(1024) int8_t g_W1q[(size_t)HH   * 3 * HH];
__device__ __align__(1024) int8_t g_Woq[(size_t)DOUT * 3 * HH];

// ---------------- helpers ----------------
__device__ __forceinline__ uint32_t smem_u32(const void* p) {
    uint32_t a;
    asm("{ .reg .u64 t; cvta.to.shared.u64 t, %1; cvt.u32.u64 %0, t; }" : "=r"(a) : "l"(p));
    return a;
}
__device__ __forceinline__ void cp16(uint32_t dst, const void* src) {
    asm volatile("cp.async.cg.shared.global [%0], [%1], 16;" :: "r"(dst), "l"(src));
}
#define CP_COMMIT() asm volatile("cp.async.commit_group;" ::: "memory")
#define CP_WAIT(n)  asm volatile("cp.async.wait_group %0;" :: "n"(n) : "memory")
#define SWZ(off) ((off) ^ (((off) >> 3) & 0x70))

__device__ __forceinline__ void ldsm4(uint32_t& r0, uint32_t& r1, uint32_t& r2, uint32_t& r3,
                                      uint32_t addr) {
    asm volatile("ldmatrix.sync.aligned.m8n8.x4.shared.b16 {%0,%1,%2,%3}, [%4];"
                 : "=r"(r0), "=r"(r1), "=r"(r2), "=r"(r3) : "r"(addr));
}
__device__ __forceinline__ void imma(int* d, const uint32_t* a, uint32_t b0, uint32_t b1) {
    asm volatile(
        "mma.sync.aligned.m16n8k32.row.col.s32.s8.s8.s32 "
        "{%0,%1,%2,%3}, {%4,%5,%6,%7}, {%8,%9}, {%0,%1,%2,%3};"
        : "+r"(d[0]), "+r"(d[1]), "+r"(d[2]), "+r"(d[3])
        : "r"(a[0]), "r"(a[1]), "r"(a[2]), "r"(a[3]), "r"(b0), "r"(b1));
}

// exact 3-limb int8 split of round(w*2^27): l2*2^16 + l1*2^8 + l0
__device__ __forceinline__ void quant_range(const float* __restrict__ W,
                                            int8_t* __restrict__ Wq,
                                            int Nw, int K, int eblk, int nblk) {
    const int total4 = (Nw * K) >> 2;
    const int KP = 3 * K;
    const int bsz = blockDim.x;
    for (int i4 = eblk * bsz + threadIdx.x; i4 < total4; i4 += nblk * bsz) {
        int idx = i4 << 2;
        int n = idx / K, k = idx - n * K;
        float4 w4 = *(const float4*)(W + idx);
        float wv[4] = {w4.x, w4.y, w4.z, w4.w};
        char l2v[4], l1v[4], l0v[4];
#pragma unroll
        for (int j = 0; j < 4; ++j) {
            long long wi = llrintf(wv[j] * 134217728.0f);   // 2^27
            int l0 = (int)((wi + 128) & 255) - 128;  wi = (wi - l0) >> 8;
            int l1 = (int)((wi + 128) & 255) - 128;  wi = (wi - l1) >> 8;
            l2v[j] = (char)wi; l1v[j] = (char)l1; l0v[j] = (char)l0;
        }
        size_t base = (size_t)n * KP + k;
        *(char4*)(Wq + base)         = make_char4(l2v[0], l2v[1], l2v[2], l2v[3]);
        *(char4*)(Wq + base + K)     = make_char4(l1v[0], l1v[1], l1v[2], l1v[3]);
        *(char4*)(Wq + base + 2 * K) = make_char4(l0v[0], l0v[1], l0v[2], l0v[3]);
    }
}

// ---------------- prep: conv_in (blocks 0..127) + quant W0 (blocks 128..159) ----------------
__global__ __launch_bounds__(PTHR)
void prep_kernel(const float* __restrict__ in, int8_t* __restrict__ A,
                 const float* __restrict__ W0, int8_t* __restrict__ W0q)
{
    const int bid = blockIdx.x;
    const int tid = threadIdx.x;
    if (bid >= 128) {
        quant_range(W0, W0q, HH, DIN, bid - 128, 32);
        return;
    }
    __shared__ int8_t sbuf[DIN * TT];   // [k][t], 16KB
    const int b = bid;
    const float4* src = (const float4*)(in + (size_t)b * DIN * TT);
    uint32_t* sb32 = (uint32_t*)sbuf;
#pragma unroll
    for (int r = 0; r < 8; ++r) {
        int j = tid + r * PTHR;          // j < 4096
        float4 v = src[j];
        uint32_t pk = (v.x > 0.5f ? 1u : 0u)
                    | (v.y > 0.5f ? 1u : 0u) << 8
                    | (v.z > 0.5f ? 1u : 0u) << 16
                    | (v.w > 0.5f ? 1u : 0u) << 24;
        sb32[j] = pk;
    }
    __syncthreads();
#pragma unroll
    for (int u = tid; u < TT * (DIN / 16); u += PTHR) {
        int t = u >> 6, kseg = u & 63;
        uint32_t w[4];
#pragma unroll
        for (int q = 0; q < 4; ++q) {
            uint32_t b0 = (uint8_t)sbuf[(kseg * 16 + q * 4 + 0) * 16 + t];
            uint32_t b1 = (uint8_t)sbuf[(kseg * 16 + q * 4 + 1) * 16 + t];
            uint32_t b2 = (uint8_t)sbuf[(kseg * 16 + q * 4 + 2) * 16 + t];
            uint32_t b3 = (uint8_t)sbuf[(kseg * 16 + q * 4 + 3) * 16 + t];
            w[q] = b0 | (b1 << 8) | (b2 << 16) | (b3 << 24);
        }
        *(uint4*)(A + ((size_t)b * TT + t) * DIN + kseg * 16) =
            make_uint4(w[0], w[1], w[2], w[3]);
    }
}

// ---------------- fused exact-GEMM (plane-split s8 IMMA) + BN + LIF ----------------
// CTA tile 128x128, 12 warps: warp (wm, wn, plane) computes a 64x64 tile of ONE limb plane.
// Planes combined exactly in the epilogue via smem. Trailing blocks do weight quant.
template<bool FINAL>
__global__ __launch_bounds__(NTHR, 1)
void gemm_lif(const int8_t* __restrict__ A,
              const int8_t* __restrict__ Wq,
              const float* __restrict__ bias, const float* __restrict__ gamma,
              const float* __restrict__ beta, const float* __restrict__ mmean,
              const float* __restrict__ mvar,
              int8_t* __restrict__ spk, float* __restrict__ out,
              int K, int N, int ntiles, int gx,
              const float* qsrc1, int8_t* qdst1, int qN1, int qK1, int qblk1,
              const float* qsrc2, int8_t* qdst2, int qN2, int qK2, int qblk2)
{
    const int bid = blockIdx.x;
    const int tid = threadIdx.x;

    if (bid >= ntiles) {               // folded weight-quant blocks
        int e = bid - ntiles;
        if (e < qblk1) quant_range(qsrc1, qdst1, qN1, qK1, e, qblk1);
        else           quant_range(qsrc2, qdst2, qN2, qK2, e - qblk1, qblk2);
        return;
    }

    const int KP  = 3 * K;
    const int nsc = K / KCB;
    const int m0  = (bid / gx) * 128;
    const int n0  = (bid % gx) * 128;

    extern __shared__ __align__(16) char dsm[];
    char* sm = (char*)(((uintptr_t)dsm + 1023) & ~(uintptr_t)1023);
    const uint32_t sm32 = smem_u32(sm);

    const int wid   = tid >> 5;
    const int lane  = tid & 31;
    const int plane = wid >> 2;        // 0 = l2(top), 1 = l1, 2 = l0
    const int sub   = wid & 3;
    const int wm    = sub & 1;         // M half
    const int wn    = sub >> 1;        // N half

    int acc[4][8][4];                  // 64x64 tile: [mf(16m)][nf(8n)][quad]
#pragma unroll
    for (int i = 0; i < 4; ++i)
#pragma unroll
        for (int j = 0; j < 8; ++j)
#pragma unroll
            for (int q = 0; q < 4; ++q) acc[i][j][q] = 0;

    const int8_t* gA = A  + (size_t)m0 * K;
    const int8_t* gB = Wq + (size_t)n0 * KP;

    auto load_chunk = [&](int c) {
        const uint32_t sbase = sm32 + (uint32_t)(c % 3) * STAGEB;
        const int koff = c * KCB;
        for (int u = tid; u < 4096; u += NTHR) {
            if (u < 1024) {            // A tile 128x128
                int r = u >> 3, q = u & 7;
                cp16(sbase + SWZ((uint32_t)(r * 128 + q * 16)),
                     gA + (size_t)r * K + koff + q * 16);
            } else {                   // 3 B planes, 128 rows each
                int v = u - 1024;
                int p = v >> 10, r = (v >> 3) & 127, q = v & 7;
                cp16(sbase + 16384 + (uint32_t)p * 16384 + SWZ((uint32_t)(r * 128 + q * 16)),
                     gB + (size_t)p * K + (size_t)r * KP + koff + q * 16);
            }
        }
    };

    load_chunk(0); CP_COMMIT();
    load_chunk(1); CP_COMMIT();

    const uint32_t aBase = (uint32_t)((wm * 64 + (lane & 7) + ((lane >> 3) & 1) * 8) * 128
                                      + ((lane >> 4) & 1) * 16);
    const uint32_t bBase = (uint32_t)((wn * 64 + (lane & 7) + ((lane >> 4) & 1) * 8) * 128
                                      + ((lane >> 3) & 1) * 16);

    for (int i = 0; i < nsc; ++i) {
        CP_WAIT(1);
        __syncthreads();

        if (i + 2 < nsc) load_chunk(i + 2);
        CP_COMMIT();

        const uint32_t sA = sm32 + (uint32_t)(i % 3) * STAGEB;
        const uint32_t sB = sA + 16384 + (uint32_t)plane * 16384;

#pragma unroll
        for (int ks = 0; ks < 4; ++ks) {
            const uint32_t kb = (uint32_t)(ks * 32);
            uint32_t a[4][4];
#pragma unroll
            for (int mf = 0; mf < 4; ++mf)
                ldsm4(a[mf][0], a[mf][1], a[mf][2], a[mf][3],
                      sA + SWZ(aBase + (uint32_t)mf * 2048 + kb));
#pragma unroll
            for (int nblk = 0; nblk < 4; ++nblk) {
                uint32_t b[4];
                ldsm4(b[0], b[1], b[2], b[3],
                      sB + SWZ(bBase + (uint32_t)nblk * 2048 + kb));
#pragma unroll
                for (int mf = 0; mf < 4; ++mf) {
                    imma(acc[mf][2 * nblk],     a[mf], b[0], b[1]);
                    imma(acc[mf][2 * nblk + 1], a[mf], b[2], b[3]);
                }
            }
        }
    }

    CP_WAIT(0);
    __syncthreads();   // stage buffers now reusable

    // ---- epilogue: cross-plane exact combine via smem ----
    // P1 (plane l1) at sm+0, P2 (plane l0) at sm+69632, both [128][136] s32.
    // scrF fp32 [128][136] at sm+139264.
    int*   P1   = (int*)sm;
    int*   P2   = (int*)(sm + 69632);
    float* scrF = (float*)(sm + 139264);

    const int rw = (lane >> 2);
    const int cw = (lane & 3) * 2;

    if (plane != 0) {
        int* P = (plane == 1) ? P1 : P2;
#pragma unroll
        for (int mf = 0; mf < 4; ++mf) {
#pragma unroll
            for (int nf = 0; nf < 8; ++nf) {
                int r = wm * 64 + mf * 16 + rw;
                int c = wn * 64 + nf * 8 + cw;
                *(int2*)&P[r * 136 + c]       = make_int2(acc[mf][nf][0], acc[mf][nf][1]);
                *(int2*)&P[(r + 8) * 136 + c] = make_int2(acc[mf][nf][2], acc[mf][nf][3]);
            }
        }
    }
    __syncthreads();

    if (plane == 0) {
        const double SL = 7.450580596923828125e-9;     // 2^-27
#pragma unroll
        for (int mf = 0; mf < 4; ++mf) {
#pragma unroll
            for (int nf = 0; nf < 8; ++nf) {
                int r = wm * 64 + mf * 16 + rw;
                int c = wn * 64 + nf * 8 + cw;
                int2 m1a = *(const int2*)&P1[r * 136 + c];
                int2 m1b = *(const int2*)&P1[(r + 8) * 136 + c];
                int2 m2a = *(const int2*)&P2[r * 136 + c];
                int2 m2b = *(const int2*)&P2[(r + 8) * 136 + c];
                float x0 = (float)(((double)acc[mf][nf][0] * 65536.0
                                  + (double)m1a.x * 256.0 + (double)m2a.x) * SL);
                float x1 = (float)(((double)acc[mf][nf][1] * 65536.0
                                  + (double)m1a.y * 256.0 + (double)m2a.y) * SL);
                float x2 = (float)(((double)acc[mf][nf][2] * 65536.0
                                  + (double)m1b.x * 256.0 + (double)m2b.x) * SL);
                float x3 = (float)(((double)acc[mf][nf][3] * 65536.0
                                  + (double)m1b.y * 256.0 + (double)m2b.y) * SL);
                *(float2*)&scrF[r * 136 + c]       = make_float2(x0, x1);
                *(float2*)&scrF[(r + 8) * 136 + c] = make_float2(x2, x3);
            }
        }
    }
    __syncthreads();

    // ---- BN + LIF (exact elementwise ops; identical to R4-R6) ----
    int8_t* scrS = (int8_t*)sm;                        // [128][144], reuses P1 region
    for (int task = tid; task < 1024; task += NTHR) {
        const int col = task & 127;
        const int bb  = task >> 7;                     // 8 b-blocks of 16 timesteps
        const int n   = n0 + col;

        const float bo  = bias[n];
        const float ga  = gamma[n];
        const float be  = beta[n];
        const float mu  = mmean[n];
        const float var = mvar[n];
        const float den = sqrtf(__fadd_rn(var, 1e-5f));

        float v = 0.0f, sp = 0.0f, cnt = 0.0f;
#pragma unroll
        for (int t = 0; t < TT; ++t) {
            float x  = scrF[(bb * 16 + t) * 136 + col];
            float u  = __fsub_rn(__fadd_rn(x, bo), mu);
            float xn = __fadd_rn(__fdiv_rn(__fmul_rn(ga, u), den), be);
            v  = __fadd_rn(__fmul_rn(__fmul_rn(v, __fsub_rn(1.0f, sp)), 0.75f), xn);
            sp = (v > 0.5f) ? 1.0f : 0.0f;
            if (FINAL) cnt += sp;
            else       scrS[(bb * 16 + t) * 144 + col] = (int8_t)sp;
        }
        if (FINAL) {
            int bg = (m0 >> 4) + bb;
            out[(size_t)bg * N + n] = cnt * 0.0625f;
        }
    }

    if (!FINAL) {
        __syncthreads();
        for (int u = tid; u < 1024; u += NTHR) {       // 128 rows x 128B, uint4 coalesced
            int r = u >> 3, seg = u & 7;
            uint4 val = *(const uint4*)(scrS + r * 144 + seg * 16);
            *(uint4*)(spk + (size_t)(m0 + r) * N + n0 + seg * 16) = val;
        }
    }
}

// ---------------- host ----------------
extern "C" void kernel_launch(void* const* d_in, const int* in_sizes, int n_in,
                              void* d_out, int out_size)
{
    const float* spk_in = (const float*)d_in[0];
    const float* W0  = (const float*)d_in[1];
    const float* b0  = (const float*)d_in[2];
    const float* g0  = (const float*)d_in[3];
    const float* be0 = (const float*)d_in[4];
    const float* mm0 = (const float*)d_in[5];
    const float* mv0 = (const float*)d_in[6];
    const float* W1  = (const float*)d_in[7];
    const float* b1  = (const float*)d_in[8];
    const float* g1  = (const float*)d_in[9];
    const float* be1 = (const float*)d_in[10];
    const float* mm1 = (const float*)d_in[11];
    const float* mv1 = (const float*)d_in[12];
    const float* Wo  = (const float*)d_in[13];
    const float* bo  = (const float*)d_in[14];
    const float* go  = (const float*)d_in[15];
    const float* beo = (const float*)d_in[16];
    const float* mmo = (const float*)d_in[17];
    const float* mvo = (const float*)d_in[18];
    float* out = (float*)d_out;

    int8_t *A0, *s0, *s1, *W0q, *W1q, *Woq;
    cudaGetSymbolAddress((void**)&A0,  g_A0);
    cudaGetSymbolAddress((void**)&s0,  g_s0);
    cudaGetSymbolAddress((void**)&s1,  g_s1);
    cudaGetSymbolAddress((void**)&W0q, g_W0q);
    cudaGetSymbolAddress((void**)&W1q, g_W1q);
    cudaGetSymbolAddress((void**)&Woq, g_Woq);

    // 3 stages (192KB) + epilogue scrF tail (overlap-extended) + align
    const int SMEM = 208896 + 1024;    // 209920 <= 227KB cap
    cudaFuncSetAttribute((const void*)gemm_lif<false>,
                         cudaFuncAttributeMaxDynamicSharedMemorySize, SMEM);
    cudaFuncSetAttribute((const void*)gemm_lif<true>,
                         cudaFuncAttributeMaxDynamicSharedMemorySize, SMEM);

    // prep: conv_in (128 blocks) + quant W0 (32 blocks)
    prep_kernel<<<160, PTHR>>>(spk_in, A0, W0, W0q);

    // Layer 0: K=1024, N=2048; 256 tiles + 96 quant blocks (W1q, Woq) in the tail
    {
        int gx = HH / 128, ntiles = gx * (MTOT / 128);   // 16 x 16 = 256
        gemm_lif<false><<<ntiles + 96, NTHR, SMEM>>>(
            A0, W0q, b0, g0, be0, mm0, mv0, s0, nullptr, DIN, HH, ntiles, gx,
            W1, W1q, HH, HH, 64,
            Wo, Woq, DOUT, HH, 32);
    }
    // Layer 1: K=2048, N=2048
    {
        int gx = HH / 128, ntiles = gx * (MTOT / 128);   // 256
        gemm_lif<false><<<ntiles, NTHR, SMEM>>>(
            s0, W1q, b1, g1, be1, mm1, mv1, s1, nullptr, HH, HH, ntiles, gx,
            nullptr, nullptr, 0, 1, 0, nullptr, nullptr, 0, 1, 0);
    }
    // Layer 2: K=2048, N=1024, final
    {
        int gx = DOUT / 128, ntiles = gx * (MTOT / 128); // 8 x 16 = 128
        gemm_lif<true><<<ntiles, NTHR, SMEM>>>(
            s1, Woq, bo, go, beo, mmo, mvo, nullptr, out, HH, DOUT, ntiles, gx,
            nullptr, nullptr, 0, 1, 0, nullptr, nullptr, 0, 1, 0);
    }
}

// round 10
// speedup vs baseline: 1.1131x; 1.1131x over previous
#include <cuda_runtime.h>
#include <cstdint>
#include <math.h>

#define TT   16
#define MTOT 2048
#define HH   2048
#define DIN  1024
#define DOUT 1024

#define NTHR 768              // 24 warps: 4(M) x 2(N) x 3(plane)
#define PTHR 512
#define KCB  128              // int8 k per chunk
#define TM   128              // CTA tile M
#define TN   64               // CTA tile N
#define STAGEB 40960          // A(16KB) + 3 B planes(8KB each)

// ---------------- static device scratch ----------------
__device__ __align__(1024) int8_t g_A0 [(size_t)MTOT * DIN];
__device__ __align__(1024) int8_t g_s0 [(size_t)MTOT * HH];
__device__ __align__(1024) int8_t g_s1 [(size_t)MTOT * HH];
__device__ __align__(1024) int8_t g_W0q[(size_t)HH   * 3 * DIN];
__device__ __align__(1024) int8_t g_W1q[(size_t)HH   * 3 * HH];
__device__ __align__(1024) int8_t g_Woq[(size_t)DOUT * 3 * HH];

// ---------------- helpers ----------------
__device__ __forceinline__ uint32_t smem_u32(const void* p) {
    uint32_t a;
    asm("{ .reg .u64 t; cvta.to.shared.u64 t, %1; cvt.u32.u64 %0, t; }" : "=r"(a) : "l"(p));
    return a;
}
__device__ __forceinline__ void cp16(uint32_t dst, const void* src) {
    asm volatile("cp.async.cg.shared.global [%0], [%1], 16;" :: "r"(dst), "l"(src));
}
#define CP_COMMIT() asm volatile("cp.async.commit_group;" ::: "memory")
#define CP_WAIT(n)  asm volatile("cp.async.wait_group %0;" :: "n"(n) : "memory")
#define SWZ(off) ((off) ^ (((off) >> 3) & 0x70))

__device__ __forceinline__ void ldsm4(uint32_t& r0, uint32_t& r1, uint32_t& r2, uint32_t& r3,
                                      uint32_t addr) {
    asm volatile("ldmatrix.sync.aligned.m8n8.x4.shared.b16 {%0,%1,%2,%3}, [%4];"
                 : "=r"(r0), "=r"(r1), "=r"(r2), "=r"(r3) : "r"(addr));
}
__device__ __forceinline__ void imma(int* d, const uint32_t* a, uint32_t b0, uint32_t b1) {
    asm volatile(
        "mma.sync.aligned.m16n8k32.row.col.s32.s8.s8.s32 "
        "{%0,%1,%2,%3}, {%4,%5,%6,%7}, {%8,%9}, {%0,%1,%2,%3};"
        : "+r"(d[0]), "+r"(d[1]), "+r"(d[2]), "+r"(d[3])
        : "r"(a[0]), "r"(a[1]), "r"(a[2]), "r"(a[3]), "r"(b0), "r"(b1));
}

// exact 3-limb int8 split of round(w*2^27): l2*2^16 + l1*2^8 + l0
__device__ __forceinline__ void quant_range(const float* __restrict__ W,
                                            int8_t* __restrict__ Wq,
                                            int Nw, int K, int eblk, int nblk) {
    const int total4 = (Nw * K) >> 2;
    const int KP = 3 * K;
    const int bsz = blockDim.x;
    for (int i4 = eblk * bsz + threadIdx.x; i4 < total4; i4 += nblk * bsz) {
        int idx = i4 << 2;
        int n = idx / K, k = idx - n * K;
        float4 w4 = *(const float4*)(W + idx);
        float wv[4] = {w4.x, w4.y, w4.z, w4.w};
        char l2v[4], l1v[4], l0v[4];
#pragma unroll
        for (int j = 0; j < 4; ++j) {
            long long wi = llrintf(wv[j] * 134217728.0f);   // 2^27
            int l0 = (int)((wi + 128) & 255) - 128;  wi = (wi - l0) >> 8;
            int l1 = (int)((wi + 128) & 255) - 128;  wi = (wi - l1) >> 8;
            l2v[j] = (char)wi; l1v[j] = (char)l1; l0v[j] = (char)l0;
        }
        size_t base = (size_t)n * KP + k;
        *(char4*)(Wq + base)         = make_char4(l2v[0], l2v[1], l2v[2], l2v[3]);
        *(char4*)(Wq + base + K)     = make_char4(l1v[0], l1v[1], l1v[2], l1v[3]);
        *(char4*)(Wq + base + 2 * K) = make_char4(l0v[0], l0v[1], l0v[2], l0v[3]);
    }
}

// ---------------- prep: conv_in (blocks 0..127) + quant W0 (blocks 128..159) ----------------
__global__ __launch_bounds__(PTHR)
void prep_kernel(const float* __restrict__ in, int8_t* __restrict__ A,
                 const float* __restrict__ W0, int8_t* __restrict__ W0q)
{
    const int bid = blockIdx.x;
    const int tid = threadIdx.x;
    if (bid >= 128) {
        quant_range(W0, W0q, HH, DIN, bid - 128, 32);
        return;
    }
    __shared__ int8_t sbuf[DIN * TT];   // [k][t], 16KB
    const int b = bid;
    const float4* src = (const float4*)(in + (size_t)b * DIN * TT);
    uint32_t* sb32 = (uint32_t*)sbuf;
#pragma unroll
    for (int r = 0; r < 8; ++r) {
        int j = tid + r * PTHR;          // j < 4096
        float4 v = src[j];
        uint32_t pk = (v.x > 0.5f ? 1u : 0u)
                    | (v.y > 0.5f ? 1u : 0u) << 8
                    | (v.z > 0.5f ? 1u : 0u) << 16
                    | (v.w > 0.5f ? 1u : 0u) << 24;
        sb32[j] = pk;
    }
    __syncthreads();
#pragma unroll
    for (int u = tid; u < TT * (DIN / 16); u += PTHR) {
        int t = u >> 6, kseg = u & 63;
        uint32_t w[4];
#pragma unroll
        for (int q = 0; q < 4; ++q) {
            uint32_t b0 = (uint8_t)sbuf[(kseg * 16 + q * 4 + 0) * 16 + t];
            uint32_t b1 = (uint8_t)sbuf[(kseg * 16 + q * 4 + 1) * 16 + t];
            uint32_t b2 = (uint8_t)sbuf[(kseg * 16 + q * 4 + 2) * 16 + t];
            uint32_t b3 = (uint8_t)sbuf[(kseg * 16 + q * 4 + 3) * 16 + t];
            w[q] = b0 | (b1 << 8) | (b2 << 16) | (b3 << 24);
        }
        *(uint4*)(A + ((size_t)b * TT + t) * DIN + kseg * 16) =
            make_uint4(w[0], w[1], w[2], w[3]);
    }
}

// ---------------- fused exact-GEMM (plane-split s8 IMMA, 24 warps) + BN + LIF ----------------
// CTA tile 128x64; warp (wm<4, wn<2, plane<3) computes a 32x32 tile of one limb plane.
// Cross-plane exact combine in epilogue. Trailing blocks do weight quant for later layers.
template<bool FINAL>
__global__ __launch_bounds__(NTHR, 1)
void gemm_lif(const int8_t* __restrict__ A,
              const int8_t* __restrict__ Wq,
              const float* __restrict__ bias, const float* __restrict__ gamma,
              const float* __restrict__ beta, const float* __restrict__ mmean,
              const float* __restrict__ mvar,
              int8_t* __restrict__ spk, float* __restrict__ out,
              int K, int N, int ntiles, int gx,
              const float* qsrc1, int8_t* qdst1, int qN1, int qK1, int qblk1,
              const float* qsrc2, int8_t* qdst2, int qN2, int qK2, int qblk2)
{
    const int bid = blockIdx.x;
    const int tid = threadIdx.x;

    if (bid >= ntiles) {               // folded weight-quant blocks (tail fill)
        int e = bid - ntiles;
        if (e < qblk1) quant_range(qsrc1, qdst1, qN1, qK1, e, qblk1);
        else           quant_range(qsrc2, qdst2, qN2, qK2, e - qblk1, qblk2);
        return;
    }

    const int KP  = 3 * K;
    const int nsc = K / KCB;
    const int m0  = (bid / gx) * TM;
    const int n0  = (bid % gx) * TN;

    extern __shared__ __align__(16) char dsm[];
    char* sm = (char*)(((uintptr_t)dsm + 1023) & ~(uintptr_t)1023);
    const uint32_t sm32 = smem_u32(sm);

    const int wid   = tid >> 5;
    const int lane  = tid & 31;
    const int plane = wid >> 3;        // 0 = l2(top), 1 = l1, 2 = l0
    const int sub   = wid & 7;
    const int wm    = sub & 3;         // 4 M groups of 32
    const int wn    = sub >> 2;        // 2 N groups of 32

    int acc[2][4][4];                  // 32x32 tile: [mf(16m)][nf(8n)][quad]
#pragma unroll
    for (int i = 0; i < 2; ++i)
#pragma unroll
        for (int j = 0; j < 4; ++j)
#pragma unroll
            for (int q = 0; q < 4; ++q) acc[i][j][q] = 0;

    const int8_t* gA = A  + (size_t)m0 * K;
    const int8_t* gB = Wq + (size_t)n0 * KP;

    auto load_chunk = [&](int c) {
        const uint32_t sbase = sm32 + (uint32_t)(c % 3) * STAGEB;
        const int koff = c * KCB;
        for (int u = tid; u < 2560; u += NTHR) {
            if (u < 1024) {            // A tile 128 rows x 128B
                int r = u >> 3, q = u & 7;
                cp16(sbase + SWZ((uint32_t)(r * 128 + q * 16)),
                     gA + (size_t)r * K + koff + q * 16);
            } else {                   // 3 B planes, 64 rows each
                int v = u - 1024;
                int p = v >> 9, r = (v >> 3) & 63, q = v & 7;
                cp16(sbase + 16384 + (uint32_t)p * 8192 + SWZ((uint32_t)(r * 128 + q * 16)),
                     gB + (size_t)p * K + (size_t)r * KP + koff + q * 16);
            }
        }
    };

    load_chunk(0); CP_COMMIT();
    load_chunk(1); CP_COMMIT();

    const uint32_t aBase = (uint32_t)((wm * 32 + (lane & 7) + ((lane >> 3) & 1) * 8) * 128
                                      + ((lane >> 4) & 1) * 16);
    const uint32_t bBase = (uint32_t)((wn * 32 + (lane & 7) + ((lane >> 4) & 1) * 8) * 128
                                      + ((lane >> 3) & 1) * 16);

    for (int i = 0; i < nsc; ++i) {
        CP_WAIT(1);
        __syncthreads();

        if (i + 2 < nsc) load_chunk(i + 2);
        CP_COMMIT();

        const uint32_t sA = sm32 + (uint32_t)(i % 3) * STAGEB;
        const uint32_t sB = sA + 16384 + (uint32_t)plane * 8192;

#pragma unroll
        for (int ks = 0; ks < 4; ++ks) {
            const uint32_t kb = (uint32_t)(ks * 32);
            uint32_t a[2][4];
#pragma unroll
            for (int mf = 0; mf < 2; ++mf)
                ldsm4(a[mf][0], a[mf][1], a[mf][2], a[mf][3],
                      sA + SWZ(aBase + (uint32_t)mf * 2048 + kb));
            uint32_t b[2][4];
#pragma unroll
            for (int nb = 0; nb < 2; ++nb)
                ldsm4(b[nb][0], b[nb][1], b[nb][2], b[nb][3],
                      sB + SWZ(bBase + (uint32_t)nb * 2048 + kb));
#pragma unroll
            for (int mf = 0; mf < 2; ++mf)
#pragma unroll
                for (int nf = 0; nf < 4; ++nf)
                    imma(acc[mf][nf], a[mf],
                         b[nf >> 1][(nf & 1) * 2], b[nf >> 1][(nf & 1) * 2 + 1]);
        }
    }

    CP_WAIT(0);
    __syncthreads();   // stage buffers now reusable

    // ---- epilogue: cross-plane exact combine via smem ----
    // P1 (l1), P2 (l0): [128][68] s32; scrF [128][68] fp32; scrS [128][80] int8.
    int*   P1   = (int*)sm;                    // 34816 B
    int*   P2   = (int*)(sm + 34816);          // 34816 B
    float* scrF = (float*)(sm + 69632);        // 34816 B
    int8_t* scrS = (int8_t*)(sm + 104448);     // 10240 B   (total 114688 <= 120KB)

    const int rw = (lane >> 2);
    const int cw = (lane & 3) * 2;

    if (plane != 0) {
        int* P = (plane == 1) ? P1 : P2;
#pragma unroll
        for (int mf = 0; mf < 2; ++mf) {
#pragma unroll
            for (int nf = 0; nf < 4; ++nf) {
                int r = wm * 32 + mf * 16 + rw;
                int c = wn * 32 + nf * 8 + cw;
                *(int2*)&P[r * 68 + c]       = make_int2(acc[mf][nf][0], acc[mf][nf][1]);
                *(int2*)&P[(r + 8) * 68 + c] = make_int2(acc[mf][nf][2], acc[mf][nf][3]);
            }
        }
    }
    __syncthreads();

    if (plane == 0) {
        const double SL = 7.450580596923828125e-9;     // 2^-27
#pragma unroll
        for (int mf = 0; mf < 2; ++mf) {
#pragma unroll
            for (int nf = 0; nf < 4; ++nf) {
                int r = wm * 32 + mf * 16 + rw;
                int c = wn * 32 + nf * 8 + cw;
                int2 m1a = *(const int2*)&P1[r * 68 + c];
                int2 m1b = *(const int2*)&P1[(r + 8) * 68 + c];
                int2 m2a = *(const int2*)&P2[r * 68 + c];
                int2 m2b = *(const int2*)&P2[(r + 8) * 68 + c];
                float x0 = (float)(((double)acc[mf][nf][0] * 65536.0
                                  + (double)m1a.x * 256.0 + (double)m2a.x) * SL);
                float x1 = (float)(((double)acc[mf][nf][1] * 65536.0
                                  + (double)m1a.y * 256.0 + (double)m2a.y) * SL);
                float x2 = (float)(((double)acc[mf][nf][2] * 65536.0
                                  + (double)m1b.x * 256.0 + (double)m2b.x) * SL);
                float x3 = (float)(((double)acc[mf][nf][3] * 65536.0
                                  + (double)m1b.y * 256.0 + (double)m2b.y) * SL);
                *(float2*)&scrF[r * 68 + c]       = make_float2(x0, x1);
                *(float2*)&scrF[(r + 8) * 68 + c] = make_float2(x2, x3);
            }
        }
    }
    __syncthreads();

    // ---- BN + LIF (exact elementwise ops, identical to R4-R7) ----
    // 512 tasks = 64 cols x 8 b-blocks
    if (tid < 512) {
        const int col = tid & 63;
        const int bb  = tid >> 6;
        const int n   = n0 + col;

        const float bo  = bias[n];
        const float ga  = gamma[n];
        const float be  = beta[n];
        const float mu  = mmean[n];
        const float var = mvar[n];
        const float den = sqrtf(__fadd_rn(var, 1e-5f));

        float v = 0.0f, sp = 0.0f, cnt = 0.0f;
#pragma unroll
        for (int t = 0; t < TT; ++t) {
            float x  = scrF[(bb * 16 + t) * 68 + col];
            float u  = __fsub_rn(__fadd_rn(x, bo), mu);
            float xn = __fadd_rn(__fdiv_rn(__fmul_rn(ga, u), den), be);
            v  = __fadd_rn(__fmul_rn(__fmul_rn(v, __fsub_rn(1.0f, sp)), 0.75f), xn);
            sp = (v > 0.5f) ? 1.0f : 0.0f;
            if (FINAL) cnt += sp;
            else       scrS[(bb * 16 + t) * 80 + col] = (int8_t)sp;
        }
        if (FINAL) {
            int bg = (m0 >> 4) + bb;
            out[(size_t)bg * N + n] = cnt * 0.0625f;
        }
    }

    if (!FINAL) {
        __syncthreads();
        if (tid < 512) {               // 128 rows x 64B, uint4 coalesced
            int r = tid >> 2, seg = tid & 3;
            uint4 val = *(const uint4*)(scrS + r * 80 + seg * 16);
            *(uint4*)(spk + (size_t)(m0 + r) * N + n0 + seg * 16) = val;
        }
    }
}

// ---------------- host ----------------
extern "C" void kernel_launch(void* const* d_in, const int* in_sizes, int n_in,
                              void* d_out, int out_size)
{
    const float* spk_in = (const float*)d_in[0];
    const float* W0  = (const float*)d_in[1];
    const float* b0  = (const float*)d_in[2];
    const float* g0  = (const float*)d_in[3];
    const float* be0 = (const float*)d_in[4];
    const float* mm0 = (const float*)d_in[5];
    const float* mv0 = (const float*)d_in[6];
    const float* W1  = (const float*)d_in[7];
    const float* b1  = (const float*)d_in[8];
    const float* g1  = (const float*)d_in[9];
    const float* be1 = (const float*)d_in[10];
    const float* mm1 = (const float*)d_in[11];
    const float* mv1 = (const float*)d_in[12];
    const float* Wo  = (const float*)d_in[13];
    const float* bo  = (const float*)d_in[14];
    const float* go  = (const float*)d_in[15];
    const float* beo = (const float*)d_in[16];
    const float* mmo = (const float*)d_in[17];
    const float* mvo = (const float*)d_in[18];
    float* out = (float*)d_out;

    int8_t *A0, *s0, *s1, *W0q, *W1q, *Woq;
    cudaGetSymbolAddress((void**)&A0,  g_A0);
    cudaGetSymbolAddress((void**)&s0,  g_s0);
    cudaGetSymbolAddress((void**)&s1,  g_s1);
    cudaGetSymbolAddress((void**)&W0q, g_W0q);
    cudaGetSymbolAddress((void**)&W1q, g_W1q);
    cudaGetSymbolAddress((void**)&Woq, g_Woq);

    const int SMEM = 3 * STAGEB + 1024;   // 123904
    cudaFuncSetAttribute((const void*)gemm_lif<false>,
                         cudaFuncAttributeMaxDynamicSharedMemorySize, SMEM);
    cudaFuncSetAttribute((const void*)gemm_lif<true>,
                         cudaFuncAttributeMaxDynamicSharedMemorySize, SMEM);

    // prep: conv_in (128 blocks) + quant W0 (32 blocks)
    prep_kernel<<<160, PTHR>>>(spk_in, A0, W0, W0q);

    // Layer 0: K=1024, N=2048; 512 tiles + 96 quant blocks (W1q, Woq) in the tail
    {
        int gx = HH / TN, ntiles = gx * (MTOT / TM);     // 32 x 16 = 512
        gemm_lif<false><<<ntiles + 96, NTHR, SMEM>>>(
            A0, W0q, b0, g0, be0, mm0, mv0, s0, nullptr, DIN, HH, ntiles, gx,
            W1, W1q, HH, HH, 64,
            Wo, Woq, DOUT, HH, 32);
    }
    // Layer 1: K=2048, N=2048
    {
        int gx = HH / TN, ntiles = gx * (MTOT / TM);     // 512
        gemm_lif<false><<<ntiles, NTHR, SMEM>>>(
            s0, W1q, b1, g1, be1, mm1, mv1, s1, nullptr, HH, HH, ntiles, gx,
            nullptr, nullptr, 0, 1, 0, nullptr, nullptr, 0, 1, 0);
    }
    // Layer 2: K=2048, N=1024, final
    {
        int gx = DOUT / TN, ntiles = gx * (MTOT / TM);   // 16 x 16 = 256
        gemm_lif<true><<<ntiles, NTHR, SMEM>>>(
            s1, Woq, bo, go, beo, mmo, mvo, nullptr, out, HH, DOUT, ntiles, gx,
            nullptr, nullptr, 0, 1, 0, nullptr, nullptr, 0, 1, 0);
    }
}

// round 12
// speedup vs baseline: 1.2056x; 1.0831x over previous
#include <cuda_runtime.h>
#include <cstdint>
#include <math.h>

#define TT   16
#define MTOT 2048
#define HH   2048
#define DIN  1024
#define DOUT 1024

#define NTHR 512
#define PTHR 512
#define KCB  128          // int8 k per super-chunk (one 128B swizzle row)

// ---------------- static device scratch ----------------
__device__ __align__(1024) int8_t g_A0 [(size_t)MTOT * DIN];
__device__ __align__(1024) int8_t g_s0 [(size_t)MTOT * HH];
__device__ __align__(1024) int8_t g_s1 [(size_t)MTOT * HH];
__device__ __align__(1024) int8_t g_W0q[(size_t)HH   * 3 * DIN];
__device__ __align__(1024) int8_t g_W1q[(size_t)HH   * 3 * HH];
__device__ __align__(1024) int8_t g_Woq[(size_t)DOUT * 3 * HH];

// ---------------- helpers ----------------
__device__ __forceinline__ uint32_t smem_u32(const void* p) {
    uint32_t a;
    asm("{ .reg .u64 t; cvta.to.shared.u64 t, %1; cvt.u32.u64 %0, t; }" : "=r"(a) : "l"(p));
    return a;
}
__device__ __forceinline__ void cp16(uint32_t dst, const void* src) {
    asm volatile("cp.async.cg.shared.global [%0], [%1], 16;" :: "r"(dst), "l"(src));
}
#define CP_COMMIT() asm volatile("cp.async.commit_group;" ::: "memory")
#define CP_WAIT(n)  asm volatile("cp.async.wait_group %0;" :: "n"(n) : "memory")
#define SWZ(off) ((off) ^ (((off) >> 3) & 0x70))

__device__ __forceinline__ void ldsm4(uint32_t& r0, uint32_t& r1, uint32_t& r2, uint32_t& r3,
                                      uint32_t addr) {
    asm volatile("ldmatrix.sync.aligned.m8n8.x4.shared.b16 {%0,%1,%2,%3}, [%4];"
                 : "=r"(r0), "=r"(r1), "=r"(r2), "=r"(r3) : "r"(addr));
}
__device__ __forceinline__ void imma(int* d, const uint32_t* a, uint32_t b0, uint32_t b1) {
    asm volatile(
        "mma.sync.aligned.m16n8k32.row.col.s32.s8.s8.s32 "
        "{%0,%1,%2,%3}, {%4,%5,%6,%7}, {%8,%9}, {%0,%1,%2,%3};"
        : "+r"(d[0]), "+r"(d[1]), "+r"(d[2]), "+r"(d[3])
        : "r"(a[0]), "r"(a[1]), "r"(a[2]), "r"(a[3]), "r"(b0), "r"(b1));
}

// exact 3-limb int8 split of round(w*2^27): l2*2^16 + l1*2^8 + l0
__device__ __forceinline__ void quant_range(const float* __restrict__ W,
                                            int8_t* __restrict__ Wq,
                                            int Nw, int K, int eblk, int nblk) {
    const int total4 = (Nw * K) >> 2;
    const int KP = 3 * K;
    const int bsz = blockDim.x;
    for (int i4 = eblk * bsz + threadIdx.x; i4 < total4; i4 += nblk * bsz) {
        int idx = i4 << 2;
        int n = idx / K, k = idx - n * K;
        float4 w4 = *(const float4*)(W + idx);
        float wv[4] = {w4.x, w4.y, w4.z, w4.w};
        char l2v[4], l1v[4], l0v[4];
#pragma unroll
        for (int j = 0; j < 4; ++j) {
            long long wi = llrintf(wv[j] * 134217728.0f);   // 2^27
            int l0 = (int)((wi + 128) & 255) - 128;  wi = (wi - l0) >> 8;
            int l1 = (int)((wi + 128) & 255) - 128;  wi = (wi - l1) >> 8;
            l2v[j] = (char)wi; l1v[j] = (char)l1; l0v[j] = (char)l0;
        }
        size_t base = (size_t)n * KP + k;
        *(char4*)(Wq + base)         = make_char4(l2v[0], l2v[1], l2v[2], l2v[3]);
        *(char4*)(Wq + base + K)     = make_char4(l1v[0], l1v[1], l1v[2], l1v[3]);
        *(char4*)(Wq + base + 2 * K) = make_char4(l0v[0], l0v[1], l0v[2], l0v[3]);
    }
}

// ---------------- prep: conv_in (blocks 0..127) + quant W0 (blocks 128..183) ----------------
__global__ __launch_bounds__(PTHR)
void prep_kernel(const float* __restrict__ in, int8_t* __restrict__ A,
                 const float* __restrict__ W0, int8_t* __restrict__ W0q)
{
    const int bid = blockIdx.x;
    const int tid = threadIdx.x;
    if (bid >= 128) {
        quant_range(W0, W0q, HH, DIN, bid - 128, 56);
        return;
    }
    __shared__ int8_t sbuf[DIN * TT];   // [k][t], 16KB
    const int b = bid;
    const float4* src = (const float4*)(in + (size_t)b * DIN * TT);
    uint32_t* sb32 = (uint32_t*)sbuf;
#pragma unroll
    for (int r = 0; r < 8; ++r) {
        int j = tid + r * PTHR;          // j < 4096
        float4 v = src[j];
        uint32_t pk = (v.x > 0.5f ? 1u : 0u)
                    | (v.y > 0.5f ? 1u : 0u) << 8
                    | (v.z > 0.5f ? 1u : 0u) << 16
                    | (v.w > 0.5f ? 1u : 0u) << 24;
        sb32[j] = pk;
    }
    __syncthreads();
#pragma unroll
    for (int u = tid; u < TT * (DIN / 16); u += PTHR) {
        int t = u >> 6, kseg = u & 63;
        uint32_t w[4];
#pragma unroll
        for (int q = 0; q < 4; ++q) {
            uint32_t b0 = (uint8_t)sbuf[(kseg * 16 + q * 4 + 0) * 16 + t];
            uint32_t b1 = (uint8_t)sbuf[(kseg * 16 + q * 4 + 1) * 16 + t];
            uint32_t b2 = (uint8_t)sbuf[(kseg * 16 + q * 4 + 2) * 16 + t];
            uint32_t b3 = (uint8_t)sbuf[(kseg * 16 + q * 4 + 3) * 16 + t];
            w[q] = b0 | (b1 << 8) | (b2 << 16) | (b3 << 24);
        }
        *(uint4*)(A + ((size_t)b * TT + t) * DIN + kseg * 16) =
            make_uint4(w[0], w[1], w[2], w[3]);
    }
}

// ---------------- fused exact-GEMM (R5 core: s8 IMMA, 3 limb planes per chunk) + BN + LIF ----------------
// CTA tile 128x128, 16 warps, each warp 32x32 x 3 planes. Trailing blocks do weight quant.
template<bool FINAL>
__global__ __launch_bounds__(NTHR, 1)
void gemm_lif(const int8_t* __restrict__ A,
              const int8_t* __restrict__ Wq,
              const float* __restrict__ bias, const float* __restrict__ gamma,
              const float* __restrict__ beta, const float* __restrict__ mmean,
              const float* __restrict__ mvar,
              int8_t* __restrict__ spk, float* __restrict__ out,
              int K, int N, int ntiles, int gx,
              const float* qsrc1, int8_t* qdst1, int qN1, int qK1, int qblk1,
              const float* qsrc2, int8_t* qdst2, int qN2, int qK2, int qblk2)
{
    const int bid = blockIdx.x;
    const int tid = threadIdx.x;

    if (bid >= ntiles) {               // folded weight-quant blocks (ragged-tail fill)
        int e = bid - ntiles;
        if (e < qblk1) quant_range(qsrc1, qdst1, qN1, qK1, e, qblk1);
        else           quant_range(qsrc2, qdst2, qN2, qK2, e - qblk1, qblk2);
        return;
    }

    const int KP  = 3 * K;
    const int nsc = K / KCB;              // super-chunks
    constexpr int ABYTES = 128 * KCB;     // 16 KB A tile
    constexpr int PBYTES = 128 * KCB;     // 16 KB per B plane
    constexpr int STAGE  = ABYTES + 3 * PBYTES;   // 64 KB

    extern __shared__ __align__(16) char dsm[];
    char* sm = (char*)(((uintptr_t)dsm + 1023) & ~(uintptr_t)1023);
    const uint32_t sm32 = smem_u32(sm);

    const int wid   = tid >> 5;
    const int lane  = tid & 31;
    const int warpM = wid & 3;            // 4 M-groups of 32
    const int warpN = wid >> 2;           // 4 N-groups of 32
    const int m0    = (bid / gx) * 128;
    const int n0    = (bid % gx) * 128;

    int acc[3][2][4][4];                  // [plane][mf][nf][quad]
#pragma unroll
    for (int p = 0; p < 3; ++p)
#pragma unroll
        for (int i = 0; i < 2; ++i)
#pragma unroll
            for (int j = 0; j < 4; ++j)
#pragma unroll
                for (int q = 0; q < 4; ++q) acc[p][i][j][q] = 0;

    auto load_chunk = [&](int c) {
        const uint32_t sbase = sm32 + (uint32_t)(c % 3) * STAGE;
        const int8_t* gA = A + (size_t)m0 * K + c * KCB;
#pragma unroll
        for (int u = tid; u < 1024; u += NTHR) {
            int r = u >> 3, q = u & 7;
            cp16(sbase + SWZ((uint32_t)(r * 128 + q * 16)), gA + (size_t)r * K + q * 16);
        }
#pragma unroll
        for (int p = 0; p < 3; ++p) {
            const int8_t* gB = Wq + (size_t)n0 * KP + p * K + c * KCB;
            const uint32_t bbase = sbase + ABYTES + (uint32_t)p * PBYTES;
#pragma unroll
            for (int u = tid; u < 1024; u += NTHR) {
                int r = u >> 3, q = u & 7;
                cp16(bbase + SWZ((uint32_t)(r * 128 + q * 16)), gB + (size_t)r * KP + q * 16);
            }
        }
    };

    load_chunk(0); CP_COMMIT();
    if (nsc > 1) { load_chunk(1); CP_COMMIT(); }
    else         { CP_COMMIT(); }

    const int aRowB = warpM * 32 + (lane & 7) + ((lane >> 3) & 1) * 8;  // + mf*16
    const int aColB = ((lane >> 4) & 1) * 16;                           // + ks*32
    const int bRowB = warpN * 32 + (lane & 7) + ((lane >> 4) & 1) * 8;  // + bg*16
    const int bColB = ((lane >> 3) & 1) * 16;                           // + ks*32

    for (int i = 0; i < nsc; ++i) {
        CP_WAIT(1);
        __syncthreads();

        if (i + 2 < nsc) load_chunk(i + 2);
        CP_COMMIT();

        const uint32_t sA = sm32 + (uint32_t)(i % 3) * STAGE;
        const uint32_t sB = sA + ABYTES;

#pragma unroll
        for (int ks = 0; ks < 4; ++ks) {
            const int kb = ks * 32;
            uint32_t a[2][4];
#pragma unroll
            for (int mf = 0; mf < 2; ++mf)
                ldsm4(a[mf][0], a[mf][1], a[mf][2], a[mf][3],
                      sA + SWZ((uint32_t)((aRowB + mf * 16) * 128 + aColB + kb)));
#pragma unroll
            for (int p = 0; p < 3; ++p) {
                uint32_t b[2][4];
#pragma unroll
                for (int bg = 0; bg < 2; ++bg)
                    ldsm4(b[bg][0], b[bg][1], b[bg][2], b[bg][3],
                          sB + (uint32_t)p * PBYTES +
                          SWZ((uint32_t)((bRowB + bg * 16) * 128 + bColB + kb)));
#pragma unroll
                for (int mf = 0; mf < 2; ++mf)
#pragma unroll
                    for (int nf = 0; nf < 4; ++nf)
                        imma(acc[p][mf][nf], a[mf],
                             b[nf >> 1][(nf & 1) * 2], b[nf >> 1][(nf & 1) * 2 + 1]);
            }
        }
    }

    CP_WAIT(0);
    __syncthreads();   // stage buffers now reusable

    // ---- exact recombine: X = (l2*2^16 + l1*2^8 + l0) * 2^-27, single fp32 rounding ----
    float* scrF = (float*)sm;                          // [128][132]
    const double SL = 7.450580596923828125e-9;         // 2^-27
    const int r0w = warpM * 32 + (lane >> 2);
    const int c0w = warpN * 32 + (lane & 3) * 2;
#pragma unroll
    for (int mf = 0; mf < 2; ++mf) {
#pragma unroll
        for (int nf = 0; nf < 4; ++nf) {
            int r = r0w + mf * 16;
            int c = c0w + nf * 8;
            float x[4];
#pragma unroll
            for (int q = 0; q < 4; ++q) {
                double s = (double)acc[0][mf][nf][q] * 65536.0
                         + (double)acc[1][mf][nf][q] * 256.0
                         + (double)acc[2][mf][nf][q];
                x[q] = (float)(s * SL);
            }
            *(float2*)&scrF[r * 132 + c]       = make_float2(x[0], x[1]);
            *(float2*)&scrF[(r + 8) * 132 + c] = make_float2(x[2], x[3]);
        }
    }
    __syncthreads();

    // ---- BN + LIF (exact elementwise ops, bit-identical to reference semantics) ----
    int8_t* scrS = (int8_t*)(sm + 67584);              // [128][144]
#pragma unroll
    for (int task = tid; task < 1024; task += NTHR) {
        const int col = task & 127;
        const int bb  = task >> 7;
        const int n   = n0 + col;

        const float bo  = bias[n];
        const float ga  = gamma[n];
        const float be  = beta[n];
        const float mu  = mmean[n];
        const float var = mvar[n];
        const float den = sqrtf(__fadd_rn(var, 1e-5f));

        float v = 0.0f, sp = 0.0f, cnt = 0.0f;
#pragma unroll
        for (int t = 0; t < TT; ++t) {
            float x  = scrF[(bb * 16 + t) * 132 + col];
            float u  = __fsub_rn(__fadd_rn(x, bo), mu);
            float xn = __fadd_rn(__fdiv_rn(__fmul_rn(ga, u), den), be);
            v  = __fadd_rn(__fmul_rn(__fmul_rn(v, __fsub_rn(1.0f, sp)), 0.75f), xn);
            sp = (v > 0.5f) ? 1.0f : 0.0f;
            if (FINAL) cnt += sp;
            else       scrS[(bb * 16 + t) * 144 + col] = (int8_t)sp;
        }
        if (FINAL) {
            int bg = (m0 >> 4) + bb;
            out[(size_t)bg * N + n] = cnt * 0.0625f;
        }
    }

    if (!FINAL) {
        __syncthreads();
#pragma unroll
        for (int u = tid; u < 1024; u += NTHR) {
            int r = u >> 3, seg = u & 7;
            uint4 val = *(const uint4*)(scrS + r * 144 + seg * 16);
            *(uint4*)(spk + (size_t)(m0 + r) * N + n0 + seg * 16) = val;
        }
    }
}

// ---------------- host ----------------
extern "C" void kernel_launch(void* const* d_in, const int* in_sizes, int n_in,
                              void* d_out, int out_size)
{
    const float* spk_in = (const float*)d_in[0];
    const float* W0  = (const float*)d_in[1];
    const float* b0  = (const float*)d_in[2];
    const float* g0  = (const float*)d_in[3];
    const float* be0 = (const float*)d_in[4];
    const float* mm0 = (const float*)d_in[5];
    const float* mv0 = (const float*)d_in[6];
    const float* W1  = (const float*)d_in[7];
    const float* b1  = (const float*)d_in[8];
    const float* g1  = (const float*)d_in[9];
    const float* be1 = (const float*)d_in[10];
    const float* mm1 = (const float*)d_in[11];
    const float* mv1 = (const float*)d_in[12];
    const float* Wo  = (const float*)d_in[13];
    const float* bo  = (const float*)d_in[14];
    const float* go  = (const float*)d_in[15];
    const float* beo = (const float*)d_in[16];
    const float* mmo = (const float*)d_in[17];
    const float* mvo = (const float*)d_in[18];
    float* out = (float*)d_out;

    int8_t *A0, *s0, *s1, *W0q, *W1q, *Woq;
    cudaGetSymbolAddress((void**)&A0,  g_A0);
    cudaGetSymbolAddress((void**)&s0,  g_s0);
    cudaGetSymbolAddress((void**)&s1,  g_s1);
    cudaGetSymbolAddress((void**)&W0q, g_W0q);
    cudaGetSymbolAddress((void**)&W1q, g_W1q);
    cudaGetSymbolAddress((void**)&Woq, g_Woq);

    const int SMEM = 3 * (4 * 128 * KCB) + 1024;   // 3 x 64KB + align = 197632
    cudaFuncSetAttribute((const void*)gemm_lif<false>,
                         cudaFuncAttributeMaxDynamicSharedMemorySize, SMEM);
    cudaFuncSetAttribute((const void*)gemm_lif<true>,
                         cudaFuncAttributeMaxDynamicSharedMemorySize, SMEM);

    // prep: conv_in (128 blocks) + quant W0 (56 blocks)
    prep_kernel<<<184, PTHR>>>(spk_in, A0, W0, W0q);

    // Layer 0: K=1024, N=2048; 256 tiles + 96 quant blocks (W1q, Woq) fill the ragged wave
    {
        int gx = HH / 128, ntiles = gx * (MTOT / 128);   // 16 x 16 = 256
        gemm_lif<false><<<ntiles + 96, NTHR, SMEM>>>(
            A0, W0q, b0, g0, be0, mm0, mv0, s0, nullptr, DIN, HH, ntiles, gx,
            W1, W1q, HH, HH, 64,
            Wo, Woq, DOUT, HH, 32);
    }
    // Layer 1: K=2048, N=2048
    {
        int gx = HH / 128, ntiles = gx * (MTOT / 128);   // 256
        gemm_lif<false><<<ntiles, NTHR, SMEM>>>(
            s0, W1q, b1, g1, be1, mm1, mv1, s1, nullptr, HH, HH, ntiles, gx,
            nullptr, nullptr, 0, 1, 0, nullptr, nullptr, 0, 1, 0);
    }
    // Layer 2: K=2048, N=1024, final
    {
        int gx = DOUT / 128, ntiles = gx * (MTOT / 128); // 8 x 16 = 128
        gemm_lif<true><<<ntiles, NTHR, SMEM>>>(
            s1, Woq, bo, go, beo, mmo, mvo, nullptr, out, HH, DOUT, ntiles, gx,
            nullptr, nullptr, 0, 1, 0, nullptr, nullptr, 0, 1, 0);
    }
}